// round 1
// baseline (speedup 1.0000x reference)
#include <cuda_runtime.h>
#include <math.h>

#define Bsz   4
#define Tq    196
#define Lseq  392
#define DM    1024
#define DI    2048
#define DS    16
#define DTR   64
#define MROWS (Bsz*Lseq)   /* 1568 */
#define M2    (Bsz*Tq)     /* 784  */

// ---------------- scratch (static device globals; no allocation) -------------
__device__ float g_temb [Bsz*DM];
__device__ float g_hmlp [Bsz*2048];
__device__ float g_embt [Bsz*DM];
__device__ float g_seq  [MROWS*DM];     // post-LN residual stream
__device__ float g_xnorm[MROWS*DM];     // rms-normed mixer input
__device__ float g_xz   [(size_t)MROWS*2*DI];
__device__ float g_xc   [(size_t)MROWS*DI];   // conv+silu output
__device__ float g_dbc  [MROWS*96];
__device__ float g_delta[(size_t)MROWS*DI];
__device__ float g_y    [(size_t)MROWS*DI];
__device__ float g_yz   [(size_t)M2*DI];
__device__ float g_mo   [(size_t)M2*DM];

// ---------------- K1: timestep embedding -------------------------------------
__global__ void k_temb(const int* __restrict__ ts) {
    int b = blockIdx.x;
    int i = threadIdx.x;                 // 512 threads
    float t = (float)ts[b];
    float freq = expf(-logf(10000.0f) * (float)i / 512.0f);
    float arg = t * freq;
    g_temb[b*DM + i]       = cosf(arg);
    g_temb[b*DM + 512 + i] = sinf(arg);
}

// ---------------- K2/K3: tiny MLP via warp-per-output GEMV -------------------
// Y[b][n] = act( X[b][:] . W[n][:] + bias[n] ),  act: 1 = silu, 0 = none
__global__ void k_mlp(const float* __restrict__ X, const float* __restrict__ W,
                      const float* __restrict__ bias, float* __restrict__ Y,
                      int K, int N, int act) {
    int warp = (blockIdx.x * blockDim.x + threadIdx.x) >> 5;
    int lane = threadIdx.x & 31;
    int b = blockIdx.y;
    if (warp >= N) return;
    const float* x = X + b*K;
    const float* w = W + (size_t)warp*K;
    float s = 0.f;
    for (int k = lane; k < K; k += 32) s = fmaf(x[k], w[k], s);
    #pragma unroll
    for (int o = 16; o; o >>= 1) s += __shfl_xor_sync(0xffffffffu, s, o);
    if (lane == 0) {
        float v = s + bias[warp];
        if (act) v = v / (1.f + expf(-v));
        Y[b*N + warp] = v;
    }
}

// ---------------- K4: build seq (embed + layernorm) and rms-norm input -------
__global__ void k_embed(const float* __restrict__ x_r, const float* __restrict__ motion,
                        const float* __restrict__ pos,
                        const float* __restrict__ ln_g, const float* __restrict__ ln_b,
                        const float* __restrict__ rms_w) {
    int l = blockIdx.x;                  // 0..391
    int b = blockIdx.y;
    int t = threadIdx.x;                 // 256
    __shared__ float r1[8], r2[8];

    float loc[4];
    float s1 = 0.f, s2 = 0.f;
    #pragma unroll
    for (int i = 0; i < 4; i++) {
        int d = t + i*256;
        float v;
        if (l < Tq) {
            v = pos[l*DM + d] + motion[(size_t)(b*Tq + l)*DM + d];
        } else {
            int lr = l - Tq;
            v = pos[lr*DM + d] + x_r[(size_t)(b*Tq + lr)*DM + d] + g_embt[b*DM + d];
        }
        loc[i] = v; s1 += v; s2 += v*v;
    }
    int lane = t & 31, w = t >> 5;
    #pragma unroll
    for (int o = 16; o; o >>= 1) { s1 += __shfl_xor_sync(~0u, s1, o); s2 += __shfl_xor_sync(~0u, s2, o); }
    if (lane == 0) { r1[w] = s1; r2[w] = s2; }
    __syncthreads();
    if (t == 0) {
        float a = 0.f, c = 0.f;
        #pragma unroll
        for (int i = 0; i < 8; i++) { a += r1[i]; c += r2[i]; }
        r1[0] = a; r2[0] = c;
    }
    __syncthreads();
    float mu = r1[0] * (1.f/DM);
    float var = r2[0] * (1.f/DM) - mu*mu;
    float rstd = rsqrtf(var + 1e-5f);
    __syncthreads();

    float q = 0.f;
    size_t row = (size_t)(b*Lseq + l)*DM;
    #pragma unroll
    for (int i = 0; i < 4; i++) {
        int d = t + i*256;
        float ln = (loc[i] - mu) * rstd * ln_g[d] + ln_b[d];
        loc[i] = ln;
        q += ln*ln;
        g_seq[row + d] = ln;
    }
    #pragma unroll
    for (int o = 16; o; o >>= 1) q += __shfl_xor_sync(~0u, q, o);
    if (lane == 0) r1[w] = q;
    __syncthreads();
    if (t == 0) {
        float a = 0.f;
        #pragma unroll
        for (int i = 0; i < 8; i++) a += r1[i];
        r1[0] = a;
    }
    __syncthreads();
    float rrms = rsqrtf(r1[0] * (1.f/DM) + 1e-5f);
    #pragma unroll
    for (int i = 0; i < 4; i++) {
        int d = t + i*256;
        g_xnorm[row + d] = loc[i] * rrms * rms_w[d];
    }
}

// ---------------- SGEMM: C[M,N] = A[M,K(lda)] . B[N,K]^T ---------------------
// 128x64 tile, BK=16, 256 threads, 8x4 per-thread microtile.
// EPI==1: softplus(v + bias[n]) epilogue.
#define BM 128
#define BN 64
#define BK 16
template<int EPI>
__global__ void sgemm(const float* __restrict__ A, const float* __restrict__ B,
                      float* __restrict__ C, int M, int N, int K, int lda,
                      const float* __restrict__ bias) {
    __shared__ float As[BK][BM];
    __shared__ float Bs[BK][BN];
    int bm0 = blockIdx.y * BM;
    int bn0 = blockIdx.x * BN;
    int tid = threadIdx.x;
    int tx = tid & 15, ty = tid >> 4;
    float acc[8][4] = {};

    for (int k0 = 0; k0 < K; k0 += BK) {
        // load A tile: 128x16 = 512 float4, 2 per thread
        #pragma unroll
        for (int u = 0; u < 2; u++) {
            int idx = tid + u*256;
            int r = idx >> 2, c4 = idx & 3;
            int gm = bm0 + r, gk = k0 + c4*4;
            float4 v = make_float4(0.f,0.f,0.f,0.f);
            if (gm < M) v = *(const float4*)&A[(size_t)gm*lda + gk];
            As[c4*4+0][r] = v.x; As[c4*4+1][r] = v.y;
            As[c4*4+2][r] = v.z; As[c4*4+3][r] = v.w;
        }
        // load B tile: 64x16 = 256 float4, 1 per thread
        {
            int r = tid >> 2, c4 = tid & 3;
            int gn = bn0 + r, gk = k0 + c4*4;
            float4 v = make_float4(0.f,0.f,0.f,0.f);
            if (gn < N) v = *(const float4*)&B[(size_t)gn*K + gk];
            Bs[c4*4+0][r] = v.x; Bs[c4*4+1][r] = v.y;
            Bs[c4*4+2][r] = v.z; Bs[c4*4+3][r] = v.w;
        }
        __syncthreads();
        #pragma unroll
        for (int k = 0; k < BK; k++) {
            float4 a0 = *(const float4*)&As[k][ty*8];
            float4 a1 = *(const float4*)&As[k][ty*8+4];
            float4 b0 = *(const float4*)&Bs[k][tx*4];
            float a[8] = {a0.x,a0.y,a0.z,a0.w,a1.x,a1.y,a1.z,a1.w};
            float bb[4] = {b0.x,b0.y,b0.z,b0.w};
            #pragma unroll
            for (int i = 0; i < 8; i++)
                #pragma unroll
                for (int j = 0; j < 4; j++)
                    acc[i][j] = fmaf(a[i], bb[j], acc[i][j]);
        }
        __syncthreads();
    }
    #pragma unroll
    for (int i = 0; i < 8; i++) {
        int m = bm0 + ty*8 + i;
        if (m >= M) continue;
        #pragma unroll
        for (int j = 0; j < 4; j++) {
            int n = bn0 + tx*4 + j;
            if (n >= N) continue;
            float v = acc[i][j];
            if (EPI == 1) {
                v += bias[n];
                v = (v > 20.f) ? v : log1pf(expf(v));
            }
            C[(size_t)m*N + n] = v;
        }
    }
}

// ---------------- K5: depthwise causal conv (w=4) + silu ---------------------
__global__ void k_conv(const float* __restrict__ cw, const float* __restrict__ cb) {
    int idx = blockIdx.x*256 + threadIdx.x;        // over 4*392*2048
    if (idx >= MROWS*DI) return;
    int e = idx & (DI-1);
    int bl = idx >> 11;                            // b*392 + l
    int l = bl % Lseq;
    const float* base = g_xz + (size_t)bl*(2*DI) + e;
    float s = cb[e];
    s = fmaf(base[0], cw[e*4+3], s);
    if (l >= 1) s = fmaf(base[-(2*DI)],   cw[e*4+2], s);
    if (l >= 2) s = fmaf(base[-2*(2*DI)], cw[e*4+1], s);
    if (l >= 3) s = fmaf(base[-3*(2*DI)], cw[e*4+0], s);
    g_xc[idx] = s / (1.f + expf(-s));
}

// ---------------- K6: selective scan (lane-per-state) ------------------------
__global__ void k_scan(const float* __restrict__ A_log) {
    int gtid = blockIdx.x*blockDim.x + threadIdx.x;   // 131072 exact
    int grp = gtid >> 4;                              // (b,e)
    int n = gtid & 15;
    int b = grp >> 11;
    int e = grp & (DI-1);
    float Ac = -expf(A_log[e*DS + n]);
    float h = 0.f;
    const float* dptr = g_delta + (size_t)b*Lseq*DI + e;
    const float* uptr = g_xc    + (size_t)b*Lseq*DI + e;
    const float* bc   = g_dbc   + (size_t)b*Lseq*96;
    float* yptr       = g_y     + (size_t)b*Lseq*DI + e;
    for (int l = 0; l < Lseq; l++) {
        float dv = dptr[(size_t)l*DI];
        float u  = uptr[(size_t)l*DI];
        float Bv = bc[l*96 + 64 + n];
        float Cv = bc[l*96 + 80 + n];
        h = fmaf(__expf(dv*Ac), h, dv*Bv*u);
        float p = h*Cv;
        p += __shfl_xor_sync(0xffffffffu, p, 1);
        p += __shfl_xor_sync(0xffffffffu, p, 2);
        p += __shfl_xor_sync(0xffffffffu, p, 4);
        p += __shfl_xor_sync(0xffffffffu, p, 8);
        if (n == 0) yptr[(size_t)l*DI] = p;
    }
}

// ---------------- K7: gate (only output half of L) ---------------------------
__global__ void k_post(const float* __restrict__ Dp) {
    int idx = blockIdx.x*256 + threadIdx.x;        // over 4*196*2048
    if (idx >= M2*DI) return;
    int e = idx & (DI-1);
    int blr = idx >> 11;                           // b*196 + lr
    int lr = blr % Tq;
    int b  = blr / Tq;
    size_t row = (size_t)(b*Lseq + Tq + lr);
    float y  = g_y [row*DI + e];
    float xc = g_xc[row*DI + e];
    float z  = g_xz[row*(2*DI) + DI + e];
    g_yz[(size_t)blr*DI + e] = (y + xc*Dp[e]) * (z / (1.f + expf(-z)));
}

// ---------------- K8: final residual + layernorm -----------------------------
__global__ void k_final(const float* __restrict__ ln_g, const float* __restrict__ ln_b,
                        float* __restrict__ out) {
    int lr = blockIdx.x;                // 0..195
    int b  = blockIdx.y;
    int t  = threadIdx.x;               // 256
    __shared__ float r1[8], r2[8];
    size_t srow = (size_t)(b*Lseq + Tq + lr)*DM;
    size_t mrow = (size_t)(b*Tq + lr)*DM;

    float loc[4];
    float s1 = 0.f, s2 = 0.f;
    #pragma unroll
    for (int i = 0; i < 4; i++) {
        int d = t + i*256;
        float v = g_seq[srow + d] + g_mo[mrow + d];
        loc[i] = v; s1 += v; s2 += v*v;
    }
    int lane = t & 31, w = t >> 5;
    #pragma unroll
    for (int o = 16; o; o >>= 1) { s1 += __shfl_xor_sync(~0u, s1, o); s2 += __shfl_xor_sync(~0u, s2, o); }
    if (lane == 0) { r1[w] = s1; r2[w] = s2; }
    __syncthreads();
    if (t == 0) {
        float a = 0.f, c = 0.f;
        #pragma unroll
        for (int i = 0; i < 8; i++) { a += r1[i]; c += r2[i]; }
        r1[0] = a; r2[0] = c;
    }
    __syncthreads();
    float mu = r1[0] * (1.f/DM);
    float var = r2[0] * (1.f/DM) - mu*mu;
    float rstd = rsqrtf(var + 1e-5f);
    #pragma unroll
    for (int i = 0; i < 4; i++) {
        int d = t + i*256;
        out[mrow + d] = (loc[i] - mu) * rstd * ln_g[d] + ln_b[d];
    }
}

// ---------------- launch ------------------------------------------------------
extern "C" void kernel_launch(void* const* d_in, const int* in_sizes, int n_in,
                              void* d_out, int out_size) {
    const float* x_r       = (const float*)d_in[0];
    const int*   timesteps = (const int*)  d_in[1];
    const float* motion    = (const float*)d_in[2];
    const float* time_w1   = (const float*)d_in[3];
    const float* time_b1   = (const float*)d_in[4];
    const float* time_w2   = (const float*)d_in[5];
    const float* time_b2   = (const float*)d_in[6];
    const float* pos_emb   = (const float*)d_in[7];
    const float* ln_g      = (const float*)d_in[8];
    const float* ln_b      = (const float*)d_in[9];
    const float* in_proj_w = (const float*)d_in[10];
    const float* conv_w    = (const float*)d_in[11];
    const float* conv_b    = (const float*)d_in[12];
    const float* x_proj_w  = (const float*)d_in[13];
    const float* dt_proj_w = (const float*)d_in[14];
    const float* dt_proj_b = (const float*)d_in[15];
    const float* A_log     = (const float*)d_in[16];
    const float* Dp        = (const float*)d_in[17];
    const float* out_proj_w= (const float*)d_in[18];
    const float* rms_w     = (const float*)d_in[19];
    float* out = (float*)d_out;

    float *p_temb, *p_h, *p_embt, *p_xnorm, *p_xz, *p_xc, *p_dbc, *p_delta, *p_yz, *p_mo;
    cudaGetSymbolAddress((void**)&p_temb,  g_temb);
    cudaGetSymbolAddress((void**)&p_h,     g_hmlp);
    cudaGetSymbolAddress((void**)&p_embt,  g_embt);
    cudaGetSymbolAddress((void**)&p_xnorm, g_xnorm);
    cudaGetSymbolAddress((void**)&p_xz,    g_xz);
    cudaGetSymbolAddress((void**)&p_xc,    g_xc);
    cudaGetSymbolAddress((void**)&p_dbc,   g_dbc);
    cudaGetSymbolAddress((void**)&p_delta, g_delta);
    cudaGetSymbolAddress((void**)&p_yz,    g_yz);
    cudaGetSymbolAddress((void**)&p_mo,    g_mo);

    // time embedding + MLP
    k_temb<<<Bsz, 512>>>(timesteps);
    k_mlp<<<dim3(2048/8, Bsz), 256>>>(p_temb, time_w1, time_b1, p_h, 1024, 2048, 1);
    k_mlp<<<dim3(1024/8, Bsz), 256>>>(p_h, time_w2, time_b2, p_embt, 2048, 1024, 0);

    // embed + LN -> seq, rms -> xnorm
    k_embed<<<dim3(Lseq, Bsz), 256>>>(x_r, motion, pos_emb, ln_g, ln_b, rms_w);

    // in_proj: xz = xnorm @ in_proj_w^T   [1568 x 4096]
    sgemm<0><<<dim3((2*2*DI)/BN, (MROWS+BM-1)/BM), 256>>>(p_xnorm, in_proj_w, p_xz,
                                                          MROWS, 2*DI, DM, DM, nullptr);
    // depthwise conv + silu
    k_conv<<<(MROWS*DI + 255)/256, 256>>>(conv_w, conv_b);

    // x_proj: dbc = xc @ x_proj_w^T   [1568 x 96]
    sgemm<0><<<dim3((96+BN-1)/BN, (MROWS+BM-1)/BM), 256>>>(p_xc, x_proj_w, p_dbc,
                                                           MROWS, 96, DI, DI, nullptr);
    // dt_proj + softplus: delta = softplus(dbc[:, :64] @ dt_proj_w^T + b)  [1568 x 2048]
    sgemm<1><<<dim3(DI/BN, (MROWS+BM-1)/BM), 256>>>(p_dbc, dt_proj_w, p_delta,
                                                    MROWS, DI, DTR, 96, dt_proj_b);
    // selective scan
    k_scan<<<(Bsz*DI*DS)/256, 256>>>(A_log);

    // gating (output half only)
    k_post<<<(M2*DI + 255)/256, 256>>>(Dp);

    // out_proj: mo = yz @ out_proj_w^T  [784 x 1024]
    sgemm<0><<<dim3(DM/BN, (M2+BM-1)/BM), 256>>>(p_yz, out_proj_w, p_mo,
                                                 M2, DM, DI, DI, nullptr);
    // residual + final LN
    k_final<<<dim3(Tq, Bsz), 256>>>(ln_g, ln_b, out);
}